// round 4
// baseline (speedup 1.0000x reference)
#include <cuda_runtime.h>
#include <cuda_bf16.h>
#include <math_constants.h>

// Problem constants
#define D        512
#define KCODES   1024
#define NMAX     16384

// GEMM-argmin tiling
#define BM 128
#define BN 128
#define BK 16
#define TM 8
#define TN 8
#define NTHREADS 256   // (BM/TM)*(BN/TN)

// Scratch (no cudaMalloc allowed)
__device__ int    g_bestIdx[NMAX];
__device__ float  g_eSq[KCODES];
__device__ float  g_xSq[NMAX];
__device__ double g_acc;

// ---------------------------------------------------------------------------
// Kernel 0: zero the loss accumulator (graph-replay safe)
// ---------------------------------------------------------------------------
__global__ void zero_kernel() {
    g_acc = 0.0;
}

// ---------------------------------------------------------------------------
// Kernel 1: eSq[k] = sum(E[k,:]^2).  Order-insensitive at the ulp scale that
// matters (esq ~1.6e-4, error ~1e-9, bucket 6.1e-5) -> tree reduce is fine.
// ---------------------------------------------------------------------------
__global__ void esq_kernel(const float* __restrict__ E) {
    int c = blockIdx.x;
    const float4* row = reinterpret_cast<const float4*>(E + (size_t)c * D);
    int t = threadIdx.x;                      // 128 threads, 128 float4s
    float4 v = row[t];
    float s = v.x * v.x + v.y * v.y + v.z * v.z + v.w * v.w;
    #pragma unroll
    for (int off = 16; off > 0; off >>= 1)
        s += __shfl_down_sync(0xFFFFFFFFu, s, off);
    __shared__ float ws[4];
    if ((t & 31) == 0) ws[t >> 5] = s;
    __syncthreads();
    if (t == 0) g_eSq[c] = ws[0] + ws[1] + ws[2] + ws[3];
}

// ---------------------------------------------------------------------------
// Kernel 1b: xSq[n] = sum(X[n,:]^2) in STRICT SEQUENTIAL fp32 order with
// rounded squares (mul then add, no FMA) -- must replicate the reference's
// fp32 reduction bit-for-bit because its low bits decide where the 6.1e-5
// quantization boundaries fall for the distance scores.
// One warp per row: coalesced load into smem, lane 0 does the ordered sum.
// ---------------------------------------------------------------------------
__global__ void xsq_kernel(const float* __restrict__ X) {
    __shared__ float buf[8][512];
    int w    = threadIdx.x >> 5;
    int lane = threadIdx.x & 31;
    int row  = blockIdx.x * 8 + w;
    const float4* src = reinterpret_cast<const float4*>(X + (size_t)row * D);
    #pragma unroll
    for (int i = 0; i < 4; i++) {
        float4 v = src[lane + 32 * i];
        *reinterpret_cast<float4*>(&buf[w][(lane + 32 * i) * 4]) = v;
    }
    __syncwarp();
    if (lane == 0) {
        float s = 0.0f;
        #pragma unroll 16
        for (int i = 0; i < 512; i++) {
            float x = buf[w][i];
            s = __fadd_rn(s, __fmul_rn(x, x));   // strict order, rounded square
        }
        g_xSq[row] = s;
    }
}

// ---------------------------------------------------------------------------
// Kernel 2: fused fp32 GEMM + argmin.
// score replicates reference EXACTLY: d = fp32(fp32(xsq + esq) - fp32(2*dot))
// (intrinsics forbid FMA contraction). First-index tie-break == jnp.argmin.
// ---------------------------------------------------------------------------
__global__ __launch_bounds__(NTHREADS, 1)
void argmin_kernel(const float* __restrict__ X,
                   const float* __restrict__ E) {
    __shared__ float As[BK][BM + 4];
    __shared__ float Bs[BK][BN + 4];

    const int tid = threadIdx.x;
    const int tx  = tid & 15;      // col group 0..15
    const int ty  = tid >> 4;      // row group 0..15
    const int rowBase = blockIdx.x * BM;

    float bestVal[TM];
    int   bestIdx[TM];
    float xs[TM];
    #pragma unroll
    for (int i = 0; i < TM; i++) {
        bestVal[i] = CUDART_INF_F;
        bestIdx[i] = 0x7fffffff;
        xs[i] = g_xSq[rowBase + ty * TM + i];
    }

    for (int nt = 0; nt < KCODES; nt += BN) {
        float acc[TM][TN];
        #pragma unroll
        for (int i = 0; i < TM; i++)
            #pragma unroll
            for (int j = 0; j < TN; j++) acc[i][j] = 0.0f;

        for (int k0 = 0; k0 < D; k0 += BK) {
            // --- load A tile (BM x BK) transposed into As[k][row] ---
            #pragma unroll
            for (int l = 0; l < 2; l++) {
                int f  = tid + l * NTHREADS;       // 0..511
                int r  = f >> 2;                   // row 0..127
                int kq = (f & 3) << 2;             // 0,4,8,12
                float4 v = *reinterpret_cast<const float4*>(
                    &X[(size_t)(rowBase + r) * D + k0 + kq]);
                As[kq + 0][r] = v.x; As[kq + 1][r] = v.y;
                As[kq + 2][r] = v.z; As[kq + 3][r] = v.w;
            }
            // --- load B tile (BN x BK) transposed into Bs[k][code] ---
            #pragma unroll
            for (int l = 0; l < 2; l++) {
                int f  = tid + l * NTHREADS;
                int r  = f >> 2;
                int kq = (f & 3) << 2;
                float4 v = *reinterpret_cast<const float4*>(
                    &E[(size_t)(nt + r) * D + k0 + kq]);
                Bs[kq + 0][r] = v.x; Bs[kq + 1][r] = v.y;
                Bs[kq + 2][r] = v.z; Bs[kq + 3][r] = v.w;
            }
            __syncthreads();

            #pragma unroll
            for (int k = 0; k < BK; k++) {
                float a[TM], b[TN];
                #pragma unroll
                for (int i = 0; i < TM; i += 4) {
                    float4 v = *reinterpret_cast<const float4*>(&As[k][ty * TM + i]);
                    a[i] = v.x; a[i+1] = v.y; a[i+2] = v.z; a[i+3] = v.w;
                }
                #pragma unroll
                for (int j = 0; j < TN; j += 4) {
                    float4 v = *reinterpret_cast<const float4*>(&Bs[k][tx * TN + j]);
                    b[j] = v.x; b[j+1] = v.y; b[j+2] = v.z; b[j+3] = v.w;
                }
                #pragma unroll
                for (int i = 0; i < TM; i++)
                    #pragma unroll
                    for (int j = 0; j < TN; j++)
                        acc[i][j] += a[i] * b[j];
            }
            __syncthreads();
        }

        // fold this code tile into the running per-thread argmin, using the
        // reference's exact fp32 expression: (xsq + esq) - 2*dot
        #pragma unroll
        for (int j = 0; j < TN; j++) {
            int   code = nt + tx * TN + j;
            float es   = g_eSq[code];
            #pragma unroll
            for (int i = 0; i < TM; i++) {
                float t2 = __fadd_rn(xs[i], es);
                float s  = __fsub_rn(t2, __fmul_rn(2.0f, acc[i][j]));
                if (s < bestVal[i] || (s == bestVal[i] && code < bestIdx[i])) {
                    bestVal[i] = s; bestIdx[i] = code;
                }
            }
        }
    }

    // cross-thread (tx) reduction per row via smem
    __shared__ float rVal[BM][17];
    __shared__ int   rIdx[BM][17];
    #pragma unroll
    for (int i = 0; i < TM; i++) {
        rVal[ty * TM + i][tx] = bestVal[i];
        rIdx[ty * TM + i][tx] = bestIdx[i];
    }
    __syncthreads();
    if (tid < BM) {
        float bv = rVal[tid][0];
        int   bi = rIdx[tid][0];
        #pragma unroll
        for (int t = 1; t < 16; t++) {
            float v  = rVal[tid][t];
            int   ix = rIdx[tid][t];
            if (v < bv || (v == bv && ix < bi)) { bv = v; bi = ix; }
        }
        g_bestIdx[rowBase + tid] = bi;
    }
}

// ---------------------------------------------------------------------------
// Kernel 3: gather quantized rows, accumulate sum((q-x)^2), emit index floats.
// outQ is offset by 1 float (loss precedes it) -> only 4B-aligned -> scalar
// stores (still coalesced). X/E loads stay float4.
// ---------------------------------------------------------------------------
__global__ void gather_kernel(const float* __restrict__ X,
                              const float* __restrict__ E,
                              float* __restrict__ outQ,
                              float* __restrict__ outIdx) {
    int row = blockIdx.x;
    int idx = g_bestIdx[row];
    const float4* e = reinterpret_cast<const float4*>(E + (size_t)idx * D);
    const float4* x = reinterpret_cast<const float4*>(X + (size_t)row * D);
    float*        q = outQ + (size_t)row * D;

    int t = threadIdx.x;                 // 128 threads, 128 float4s per row
    float4 ev = e[t], xv = x[t];
    q[t * 4 + 0] = ev.x;
    q[t * 4 + 1] = ev.y;
    q[t * 4 + 2] = ev.z;
    q[t * 4 + 3] = ev.w;
    float dx = ev.x - xv.x, dy = ev.y - xv.y, dz = ev.z - xv.z, dw = ev.w - xv.w;
    float s = dx * dx + dy * dy + dz * dz + dw * dw;

    #pragma unroll
    for (int off = 16; off > 0; off >>= 1)
        s += __shfl_down_sync(0xFFFFFFFFu, s, off);
    __shared__ float ws[4];
    if ((t & 31) == 0) ws[t >> 5] = s;
    __syncthreads();
    if (t == 0) {
        atomicAdd(&g_acc, (double)(ws[0] + ws[1] + ws[2] + ws[3]));
        outIdx[row] = (float)idx;
    }
}

// ---------------------------------------------------------------------------
// Kernel 4: finalize loss = 1.25 * mean((q-x)^2)
// ---------------------------------------------------------------------------
__global__ void finalize_kernel(float* __restrict__ outLoss, int n) {
    outLoss[0] = (float)(1.25 * g_acc / ((double)n * (double)D));
}

// ---------------------------------------------------------------------------
extern "C" void kernel_launch(void* const* d_in, const int* in_sizes, int n_in,
                              void* d_out, int out_size) {
    const float* X = (const float*)d_in[0];   // [64,256,512] -> [N, D]
    const float* E = (const float*)d_in[1];   // [1024, 512]

    const int N = in_sizes[0] / D;            // 16384

    float* out      = (float*)d_out;
    float* outLoss  = out;                    // [1]
    float* outQ     = out + 1;                // [N*D]
    float* outIdx   = out + 1 + (size_t)N * D;// [N]

    zero_kernel<<<1, 1>>>();
    esq_kernel<<<KCODES, 128>>>(E);
    xsq_kernel<<<N / 8, 256>>>(X);
    argmin_kernel<<<N / BM, NTHREADS>>>(X, E);
    gather_kernel<<<N, 128>>>(X, E, outQ, outIdx);
    finalize_kernel<<<1, 1>>>(outLoss, N);
}

// round 7
// speedup vs baseline: 3.6007x; 3.6007x over previous
#include <cuda_runtime.h>
#include <cuda_bf16.h>
#include <math_constants.h>
#include <cstdint>

// Problem constants
#define D        512
#define KCODES   1024
#define NMAX     16384
#define MARGIN   2e-3f

// ---------------------------------------------------------------------------
// Scratch (device globals; no cudaMalloc allowed)
// ---------------------------------------------------------------------------
__device__ float  g_eSq[KCODES];
__device__ float  g_xSq[NMAX];
__device__ double g_acc;
__device__ float  g_scores[(size_t)NMAX * KCODES];   // 64 MB screening scores

// ---------------------------------------------------------------------------
// PTX wrappers (base-target instructions only: ldmatrix / mma.sync)
// ---------------------------------------------------------------------------
__device__ __forceinline__ uint32_t smem_u32(const void* p) {
    uint32_t a;
    asm("{ .reg .u64 t; cvta.to.shared.u64 t, %1; cvt.u32.u64 %0, t; }"
        : "=r"(a) : "l"(p));
    return a;
}

__device__ __forceinline__ void ldmatrix_x4(uint32_t r[4], uint32_t addr) {
    asm volatile("ldmatrix.sync.aligned.m8n8.x4.shared.b16 {%0,%1,%2,%3}, [%4];"
                 : "=r"(r[0]), "=r"(r[1]), "=r"(r[2]), "=r"(r[3]) : "r"(addr));
}
__device__ __forceinline__ void ldmatrix_x2(uint32_t r[2], uint32_t addr) {
    asm volatile("ldmatrix.sync.aligned.m8n8.x2.shared.b16 {%0,%1}, [%2];"
                 : "=r"(r[0]), "=r"(r[1]) : "r"(addr));
}
__device__ __forceinline__ void mma_bf16(float d[4], const uint32_t a[4],
                                         const uint32_t b[2]) {
    asm volatile(
        "mma.sync.aligned.m16n8k16.row.col.f32.bf16.bf16.f32 "
        "{%0,%1,%2,%3}, {%4,%5,%6,%7}, {%8,%9}, {%0,%1,%2,%3};"
        : "+f"(d[0]), "+f"(d[1]), "+f"(d[2]), "+f"(d[3])
        : "r"(a[0]), "r"(a[1]), "r"(a[2]), "r"(a[3]), "r"(b[0]), "r"(b[1]));
}

// ---------------------------------------------------------------------------
// Kernel 0: zero the loss accumulator
// ---------------------------------------------------------------------------
__global__ void zero_kernel() { g_acc = 0.0; }

// ---------------------------------------------------------------------------
// Kernel 1: eSq[k] = sum(E[k,:]^2) (tree order fine: err ~1e-9 << 6.1e-5 ulp)
// ---------------------------------------------------------------------------
__global__ void esq_kernel(const float* __restrict__ E) {
    int c = blockIdx.x;
    const float4* row = reinterpret_cast<const float4*>(E + (size_t)c * D);
    int t = threadIdx.x;
    float4 v = row[t];
    float s = v.x * v.x + v.y * v.y + v.z * v.z + v.w * v.w;
    #pragma unroll
    for (int off = 16; off > 0; off >>= 1)
        s += __shfl_down_sync(0xFFFFFFFFu, s, off);
    __shared__ float ws[4];
    if ((t & 31) == 0) ws[t >> 5] = s;
    __syncthreads();
    if (t == 0) g_eSq[c] = ws[0] + ws[1] + ws[2] + ws[3];
}

// ---------------------------------------------------------------------------
// Kernel 1b: xSq[n] = strict sequential fp32 sum of squares (matches reference
// rounding; low bits set where the quantization boundaries fall).
// ---------------------------------------------------------------------------
__global__ void xsq_kernel(const float* __restrict__ X) {
    __shared__ float buf[8][512];
    int w    = threadIdx.x >> 5;
    int lane = threadIdx.x & 31;
    int row  = blockIdx.x * 8 + w;
    const float4* src = reinterpret_cast<const float4*>(X + (size_t)row * D);
    #pragma unroll
    for (int i = 0; i < 4; i++) {
        float4 v = src[lane + 32 * i];
        *reinterpret_cast<float4*>(&buf[w][(lane + 32 * i) * 4]) = v;
    }
    __syncwarp();
    if (lane == 0) {
        float s = 0.0f;
        #pragma unroll 16
        for (int i = 0; i < 512; i++) {
            float x = buf[w][i];
            s = __fadd_rn(s, __fmul_rn(x, x));
        }
        g_xSq[row] = s;
    }
}

// ---------------------------------------------------------------------------
// Kernel 2: SCREEN — bf16 mma.sync GEMM writing s = esq - 2*dot for all pairs.
// 128 CTAs x 256 threads. A (128x512 bf16) persistent in smem; B double-
// buffered in K-chunks of 64. Warp tile 64x32 via m16n8k16.
// smem: A 128*520*2 = 133120 | B 2*128*72*2 = 36864 | esq 4096  -> 174080 B
// ---------------------------------------------------------------------------
#define A_STRIDE 520     // halves per row (pad 8): conflict-free ldmatrix
#define B_STRIDE 72
#define SM_A_BYTES   (128 * A_STRIDE * 2)
#define SM_B_BYTES   (2 * 128 * B_STRIDE * 2)
#define SM_SCR_TOTAL (SM_A_BYTES + SM_B_BYTES + 4096)

__global__ __launch_bounds__(256, 1)
void screen_kernel(const float* __restrict__ X, const float* __restrict__ E) {
    extern __shared__ char sm[];
    __nv_bfloat16* Asm = reinterpret_cast<__nv_bfloat16*>(sm);
    __nv_bfloat16* Bsm = reinterpret_cast<__nv_bfloat16*>(sm + SM_A_BYTES);
    float*         esm = reinterpret_cast<float*>(sm + SM_A_BYTES + SM_B_BYTES);

    const int tid  = threadIdx.x;
    const int lane = tid & 31;
    const int wid  = tid >> 5;
    const int wm   = wid >> 2;          // 0..1  (m warp tile of 64 rows)
    const int wn   = wid & 3;           // 0..3  (n warp tile of 32 codes)
    const int rowBase = blockIdx.x * 128;

    for (int i = tid; i < KCODES; i += 256) esm[i] = g_eSq[i];

    // --- load + convert A: X[rowBase..+128][0..512) -> bf16 smem ---
    #pragma unroll 4
    for (int i = 0; i < 64; i++) {
        int f = tid + i * 256;          // float4 id: 128 per row
        int r = f >> 7;
        int k = (f & 127) << 2;
        float4 v = *reinterpret_cast<const float4*>(&X[(size_t)(rowBase + r) * D + k]);
        __nv_bfloat162 p0 = __floats2bfloat162_rn(v.x, v.y);
        __nv_bfloat162 p1 = __floats2bfloat162_rn(v.z, v.w);
        *reinterpret_cast<__nv_bfloat162*>(&Asm[r * A_STRIDE + k])     = p0;
        *reinterpret_cast<__nv_bfloat162*>(&Asm[r * A_STRIDE + k + 2]) = p1;
    }
    __syncthreads();

    const uint32_t sA = smem_u32(Asm);
    const uint32_t sB = smem_u32(Bsm);

    // per-lane ldmatrix address components
    const int aRowLane = ((lane >> 3) & 1) * 8 + (lane & 7);
    const int aKLane   = ((lane >> 4) & 1) * 8;
    const int bRowLane = lane & 7;
    const int bKLane   = ((lane >> 3) & 1) * 8;

    for (int nt = 0; nt < 8; nt++) {
        const int nbase = nt * 128;
        float acc[4][4][4];
        #pragma unroll
        for (int mi = 0; mi < 4; mi++)
            #pragma unroll
            for (int ni = 0; ni < 4; ni++)
                #pragma unroll
                for (int q = 0; q < 4; q++) acc[mi][ni][q] = 0.0f;

        // prologue: chunk 0 -> buf0
        float4 stg[8];
        {
            #pragma unroll
            for (int i = 0; i < 8; i++) {
                int f = tid + i * 256;      // float4 id within chunk (16/row)
                int r = f >> 4;
                int k = (f & 15) << 2;
                stg[i] = *reinterpret_cast<const float4*>(
                    &E[(size_t)(nbase + r) * D + 0 + k]);
            }
            #pragma unroll
            for (int i = 0; i < 8; i++) {
                int f = tid + i * 256;
                int r = f >> 4;
                int k = (f & 15) << 2;
                __nv_bfloat162 p0 = __floats2bfloat162_rn(stg[i].x, stg[i].y);
                __nv_bfloat162 p1 = __floats2bfloat162_rn(stg[i].z, stg[i].w);
                *reinterpret_cast<__nv_bfloat162*>(&Bsm[r * B_STRIDE + k])     = p0;
                *reinterpret_cast<__nv_bfloat162*>(&Bsm[r * B_STRIDE + k + 2]) = p1;
            }
        }
        __syncthreads();

        for (int c = 0; c < 8; c++) {
            // stage next chunk's gmem loads (latency overlapped with mma)
            if (c < 7) {
                int kc = (c + 1) * 64;
                #pragma unroll
                for (int i = 0; i < 8; i++) {
                    int f = tid + i * 256;
                    int r = f >> 4;
                    int k = (f & 15) << 2;
                    stg[i] = *reinterpret_cast<const float4*>(
                        &E[(size_t)(nbase + r) * D + kc + k]);
                }
            }

            const uint32_t bufA = sB + (uint32_t)(c & 1) * (128 * B_STRIDE * 2);
            #pragma unroll
            for (int ks = 0; ks < 4; ks++) {
                uint32_t afr[4][4];
                const int kk = c * 64 + ks * 16 + aKLane;
                #pragma unroll
                for (int mi = 0; mi < 4; mi++) {
                    int r = wm * 64 + mi * 16 + aRowLane;
                    ldmatrix_x4(afr[mi], sA + (uint32_t)(r * A_STRIDE + kk) * 2);
                }
                uint32_t bfr[4][2];
                const int kb = ks * 16 + bKLane;
                #pragma unroll
                for (int ni = 0; ni < 4; ni++) {
                    int r = wn * 32 + ni * 8 + bRowLane;
                    ldmatrix_x2(bfr[ni], bufA + (uint32_t)(r * B_STRIDE + kb) * 2);
                }
                #pragma unroll
                for (int mi = 0; mi < 4; mi++)
                    #pragma unroll
                    for (int ni = 0; ni < 4; ni++)
                        mma_bf16(acc[mi][ni], afr[mi], bfr[ni]);
            }
            __syncthreads();
            if (c < 7) {
                __nv_bfloat16* dst = Bsm + ((c + 1) & 1) * (128 * B_STRIDE);
                #pragma unroll
                for (int i = 0; i < 8; i++) {
                    int f = tid + i * 256;
                    int r = f >> 4;
                    int k = (f & 15) << 2;
                    __nv_bfloat162 p0 = __floats2bfloat162_rn(stg[i].x, stg[i].y);
                    __nv_bfloat162 p1 = __floats2bfloat162_rn(stg[i].z, stg[i].w);
                    *reinterpret_cast<__nv_bfloat162*>(&dst[r * B_STRIDE + k])     = p0;
                    *reinterpret_cast<__nv_bfloat162*>(&dst[r * B_STRIDE + k + 2]) = p1;
                }
                __syncthreads();
            }
        }

        // epilogue: s = esq - 2*dot  ->  g_scores[row][code]
        #pragma unroll
        for (int mi = 0; mi < 4; mi++) {
            int r0 = rowBase + wm * 64 + mi * 16 + (lane >> 2);
            #pragma unroll
            for (int ni = 0; ni < 4; ni++) {
                int col = nbase + wn * 32 + ni * 8 + (lane & 3) * 2;
                float es0 = esm[col], es1 = esm[col + 1];
                float2 lo = make_float2(es0 - 2.0f * acc[mi][ni][0],
                                        es1 - 2.0f * acc[mi][ni][1]);
                float2 hi = make_float2(es0 - 2.0f * acc[mi][ni][2],
                                        es1 - 2.0f * acc[mi][ni][3]);
                *reinterpret_cast<float2*>(&g_scores[(size_t)r0 * KCODES + col])       = lo;
                *reinterpret_cast<float2*>(&g_scores[(size_t)(r0 + 8) * KCODES + col]) = hi;
            }
        }
    }
}

// ---------------------------------------------------------------------------
// Kernel 3: SELECT + EXACT + GATHER + LOSS.  One block (128 thr) per row.
//  - find screened min; candidates = { s < min + MARGIN }  (superset proof:
//    |screen-true| << MARGIN)
//  - exact fp32 dot for candidates; quantized score fl((xsq+esq)-fl(2*dot));
//    argmin with first-index tie-break == reference
//  - write quantized row (scalar stores: outQ only 4B-aligned), index, loss
// ---------------------------------------------------------------------------
#define MAXCAND 32
__global__ __launch_bounds__(128)
void select_kernel(const float* __restrict__ X, const float* __restrict__ E,
                   float* __restrict__ outQ, float* __restrict__ outIdx) {
    const int row  = blockIdx.x;
    const int t    = threadIdx.x;
    const int lane = t & 31;
    const int wid  = t >> 5;

    __shared__ float xrow[512];
    __shared__ float wred[4];
    __shared__ int   cand[MAXCAND];
    __shared__ float cval[MAXCAND];
    __shared__ int   ccnt;
    __shared__ int   bestIdx_s;
    __shared__ float fbV[128];
    __shared__ int   fbI[128];

    // load X row (float4 -> smem)
    float4 xv = reinterpret_cast<const float4*>(X + (size_t)row * D)[t];
    *reinterpret_cast<float4*>(&xrow[t * 4]) = xv;
    if (t == 0) ccnt = 0;

    // load scores, local min
    const float* srow = g_scores + (size_t)row * KCODES;
    float4 sa = reinterpret_cast<const float4*>(srow)[t];
    float4 sb = reinterpret_cast<const float4*>(srow)[t + 128];
    float m = fminf(fminf(fminf(sa.x, sa.y), fminf(sa.z, sa.w)),
                    fminf(fminf(sb.x, sb.y), fminf(sb.z, sb.w)));
    #pragma unroll
    for (int off = 16; off > 0; off >>= 1)
        m = fminf(m, __shfl_xor_sync(0xFFFFFFFFu, m, off));
    if (lane == 0) wred[wid] = m;
    __syncthreads();
    m = fminf(fminf(wred[0], wred[1]), fminf(wred[2], wred[3]));
    const float thresh = m + MARGIN;

    // collect candidates
    float sv[8] = {sa.x, sa.y, sa.z, sa.w, sb.x, sb.y, sb.z, sb.w};
    #pragma unroll
    for (int j = 0; j < 8; j++) {
        int code = (j < 4) ? (t * 4 + j) : (512 + t * 4 + (j - 4));
        if (sv[j] < thresh) {
            int slot = atomicAdd(&ccnt, 1);
            if (slot < MAXCAND) cand[slot] = code;
        }
    }
    __syncthreads();
    int cnt = ccnt;
    const float xs = g_xSq[row];

    if (cnt <= MAXCAND) {
        // exact per candidate: warp w handles candidates w, w+4, ...
        for (int i = wid; i < cnt; i += 4) {
            int code = cand[i];
            const float* e = E + (size_t)code * D;
            float p = 0.0f;
            #pragma unroll 4
            for (int j = lane; j < D; j += 32) p = fmaf(xrow[j], e[j], p);
            #pragma unroll
            for (int off = 16; off > 0; off >>= 1)
                p += __shfl_xor_sync(0xFFFFFFFFu, p, off);
            if (lane == 0)
                cval[i] = __fsub_rn(__fadd_rn(xs, g_eSq[code]),
                                    __fmul_rn(2.0f, p));
        }
        __syncthreads();
        if (t == 0) {
            float bv = CUDART_INF_F; int bi = 0x7fffffff;
            for (int i = 0; i < cnt; i++) {
                float v = cval[i]; int ix = cand[i];
                if (v < bv || (v == bv && ix < bi)) { bv = v; bi = ix; }
            }
            bestIdx_s = bi;
        }
    } else {
        // overflow fallback (rare): full exact scan, 8 codes per thread
        float bv = CUDART_INF_F; int bi = 0x7fffffff;
        for (int j = 0; j < 8; j++) {
            int code = t * 8 + j;
            const float* e = E + (size_t)code * D;
            float p = 0.0f;
            for (int k = 0; k < D; k++) p = fmaf(xrow[k], e[k], p);
            float v = __fsub_rn(__fadd_rn(xs, g_eSq[code]), __fmul_rn(2.0f, p));
            if (v < bv || (v == bv && code < bi)) { bv = v; bi = code; }
        }
        fbV[t] = bv; fbI[t] = bi;
        __syncthreads();
        if (t == 0) {
            for (int i = 1; i < 128; i++) {
                if (fbV[i] < bv || (fbV[i] == bv && fbI[i] < bi)) {
                    bv = fbV[i]; bi = fbI[i];
                }
            }
            bestIdx_s = bi;
        }
    }
    __syncthreads();
    const int bi = bestIdx_s;

    // gather + loss
    float4 ev = reinterpret_cast<const float4*>(E + (size_t)bi * D)[t];
    float* q = outQ + (size_t)row * D;
    q[t * 4 + 0] = ev.x; q[t * 4 + 1] = ev.y;
    q[t * 4 + 2] = ev.z; q[t * 4 + 3] = ev.w;
    float dx = ev.x - xv.x, dy = ev.y - xv.y, dz = ev.z - xv.z, dw = ev.w - xv.w;
    float s = dx * dx + dy * dy + dz * dz + dw * dw;
    #pragma unroll
    for (int off = 16; off > 0; off >>= 1)
        s += __shfl_down_sync(0xFFFFFFFFu, s, off);
    if (lane == 0) wred[wid] = s;
    __syncthreads();
    if (t == 0) {
        atomicAdd(&g_acc, (double)(wred[0] + wred[1] + wred[2] + wred[3]));
        outIdx[row] = (float)bi;
    }
}

// ---------------------------------------------------------------------------
// Kernel 4: finalize loss = 1.25 * mean((q-x)^2)
// ---------------------------------------------------------------------------
__global__ void finalize_kernel(float* __restrict__ outLoss, int n) {
    outLoss[0] = (float)(1.25 * g_acc / ((double)n * (double)D));
}

// ---------------------------------------------------------------------------
extern "C" void kernel_launch(void* const* d_in, const int* in_sizes, int n_in,
                              void* d_out, int out_size) {
    const float* X = (const float*)d_in[0];   // [N, 512]
    const float* E = (const float*)d_in[1];   // [1024, 512]

    const int N = in_sizes[0] / D;            // 16384

    float* out      = (float*)d_out;
    float* outLoss  = out;
    float* outQ     = out + 1;
    float* outIdx   = out + 1 + (size_t)N * D;

    cudaFuncSetAttribute(screen_kernel,
                         cudaFuncAttributeMaxDynamicSharedMemorySize, SM_SCR_TOTAL);

    zero_kernel<<<1, 1>>>();
    esq_kernel<<<KCODES, 128>>>(E);
    xsq_kernel<<<N / 8, 256>>>(X);
    screen_kernel<<<N / 128, 256, SM_SCR_TOTAL>>>(X, E);
    select_kernel<<<N, 128>>>(X, E, outQ, outIdx);
    finalize_kernel<<<1, 1>>>(outLoss, N);
}

// round 9
// speedup vs baseline: 3.9639x; 1.1009x over previous
#include <cuda_runtime.h>
#include <cuda_bf16.h>
#include <math_constants.h>
#include <cstdint>

// Problem constants
#define D        512
#define KCODES   1024
#define NMAX     16384
#define MARGIN   2e-3f

// ---------------------------------------------------------------------------
// Scratch (device globals; no cudaMalloc allowed)
// ---------------------------------------------------------------------------
__device__ float         g_eSq[KCODES];
__device__ float         g_xSq[NMAX];
__device__ double        g_acc;
__device__ __align__(16) __nv_bfloat16 g_Ebf[(size_t)KCODES * D];        // 1 MB
__device__ __align__(16) __nv_bfloat16 g_scoresh[(size_t)NMAX * KCODES]; // 32 MB

// ---------------------------------------------------------------------------
// PTX wrappers (base-target instructions only: ldmatrix / mma.sync / cp.async)
// ---------------------------------------------------------------------------
__device__ __forceinline__ uint32_t smem_u32(const void* p) {
    uint32_t a;
    asm("{ .reg .u64 t; cvta.to.shared.u64 t, %1; cvt.u32.u64 %0, t; }"
        : "=r"(a) : "l"(p));
    return a;
}
__device__ __forceinline__ void ldmatrix_x4(uint32_t r[4], uint32_t addr) {
    asm volatile("ldmatrix.sync.aligned.m8n8.x4.shared.b16 {%0,%1,%2,%3}, [%4];"
                 : "=r"(r[0]), "=r"(r[1]), "=r"(r[2]), "=r"(r[3]) : "r"(addr));
}
__device__ __forceinline__ void ldmatrix_x2(uint32_t r[2], uint32_t addr) {
    asm volatile("ldmatrix.sync.aligned.m8n8.x2.shared.b16 {%0,%1}, [%2];"
                 : "=r"(r[0]), "=r"(r[1]) : "r"(addr));
}
__device__ __forceinline__ void mma_bf16(float d[4], const uint32_t a[4],
                                         const uint32_t b[2]) {
    asm volatile(
        "mma.sync.aligned.m16n8k16.row.col.f32.bf16.bf16.f32 "
        "{%0,%1,%2,%3}, {%4,%5,%6,%7}, {%8,%9}, {%0,%1,%2,%3};"
        : "+f"(d[0]), "+f"(d[1]), "+f"(d[2]), "+f"(d[3])
        : "r"(a[0]), "r"(a[1]), "r"(a[2]), "r"(a[3]), "r"(b[0]), "r"(b[1]));
}
#define CP_ASYNC16(dst, src) \
    asm volatile("cp.async.cg.shared.global [%0], [%1], 16;" \
                 :: "r"(dst), "l"(src) : "memory")
#define CP_COMMIT() asm volatile("cp.async.commit_group;" ::: "memory")
#define CP_WAIT(n)  asm volatile("cp.async.wait_group %0;" :: "n"(n) : "memory")

// ---------------------------------------------------------------------------
// Kernel 0: zero the loss accumulator
// ---------------------------------------------------------------------------
__global__ void zero_kernel() { g_acc = 0.0; }

// ---------------------------------------------------------------------------
// Kernel 1: eSq[k] = sum(E[k,:]^2)  AND  E -> bf16 (fused: E already in flight)
// ---------------------------------------------------------------------------
__global__ void esq_kernel(const float* __restrict__ E) {
    int c = blockIdx.x;
    const float4* row = reinterpret_cast<const float4*>(E + (size_t)c * D);
    int t = threadIdx.x;
    float4 v = row[t];
    __nv_bfloat162 p0 = __floats2bfloat162_rn(v.x, v.y);
    __nv_bfloat162 p1 = __floats2bfloat162_rn(v.z, v.w);
    *reinterpret_cast<__nv_bfloat162*>(&g_Ebf[(size_t)c * D + t * 4])     = p0;
    *reinterpret_cast<__nv_bfloat162*>(&g_Ebf[(size_t)c * D + t * 4 + 2]) = p1;

    float s = v.x * v.x + v.y * v.y + v.z * v.z + v.w * v.w;
    #pragma unroll
    for (int off = 16; off > 0; off >>= 1)
        s += __shfl_down_sync(0xFFFFFFFFu, s, off);
    __shared__ float ws[4];
    if ((t & 31) == 0) ws[t >> 5] = s;
    __syncthreads();
    if (t == 0) g_eSq[c] = ws[0] + ws[1] + ws[2] + ws[3];
}

// ---------------------------------------------------------------------------
// Kernel 1b: xSq[n] = strict sequential fp32 sum of squares (matches reference
// rounding; low bits set where the quantization boundaries fall).
// ---------------------------------------------------------------------------
__global__ void xsq_kernel(const float* __restrict__ X) {
    __shared__ float buf[8][512];
    int w    = threadIdx.x >> 5;
    int lane = threadIdx.x & 31;
    int row  = blockIdx.x * 8 + w;
    const float4* src = reinterpret_cast<const float4*>(X + (size_t)row * D);
    #pragma unroll
    for (int i = 0; i < 4; i++) {
        float4 v = src[lane + 32 * i];
        *reinterpret_cast<float4*>(&buf[w][(lane + 32 * i) * 4]) = v;
    }
    __syncwarp();
    if (lane == 0) {
        float s = 0.0f;
        #pragma unroll 16
        for (int i = 0; i < 512; i++) {
            float x = buf[w][i];
            s = __fadd_rn(s, __fmul_rn(x, x));
        }
        g_xSq[row] = s;
    }
}

// ---------------------------------------------------------------------------
// Kernel 2: SCREEN — bf16 mma.sync GEMM, s = esq - 2*dot, bf16 score matrix.
// 128 CTAs x 256 threads. A (128x512 bf16) persistent in smem; B streamed
// via 4-stage cp.async pipeline (stage = 128 codes x 64 K-cols bf16).
// Steps s=0..63: nt = s>>3 (code tile of 128), c = s&7 (K chunk of 64).
// One __syncthreads per step:  wait(2) -> sync -> issue(s+3) -> compute(s).
// ---------------------------------------------------------------------------
#define A_STRIDE 520          // halves per row (pad 8): conflict-free ldmatrix
#define B_STRIDE 72           // halves per row (144 B = 16B-aligned, 4-bank skew)
#define NSTAGE   4
#define BSTG_HALVES (128 * B_STRIDE)
#define SM_A_BYTES   (128 * A_STRIDE * 2)                 // 133120
#define SM_B_BYTES   (NSTAGE * BSTG_HALVES * 2)           // 73728
#define SM_SCR_TOTAL (SM_A_BYTES + SM_B_BYTES + 4096)     // 210944

__global__ __launch_bounds__(256, 1)
void screen_kernel(const float* __restrict__ X) {
    extern __shared__ char sm[];
    __nv_bfloat16* Asm = reinterpret_cast<__nv_bfloat16*>(sm);
    float*         esm = reinterpret_cast<float*>(sm + SM_A_BYTES + SM_B_BYTES);

    const int tid  = threadIdx.x;
    const int lane = tid & 31;
    const int wid  = tid >> 5;
    const int wm   = wid >> 2;          // 0..1  (m warp tile of 64 rows)
    const int wn   = wid & 3;           // 0..3  (n warp tile of 32 codes)
    const int rowBase = blockIdx.x * 128;

    const uint32_t sA = smem_u32(sm);
    const uint32_t sB = sA + SM_A_BYTES;

    // cp.async issue for pipeline step s (uniform across threads)
    const int ldR  = tid >> 3;          // 0..31 (row group; 4 rows per thread)
    const int ldKq = (tid & 7) * 8;     // 16B chunk within 64-col stage row
    auto issue = [&](int s) {
        if (s < 64) {
            int nt = s >> 3, c = s & 7;
            // BUGFIX (R7): per-thread row offset ldR*D was missing from src.
            const __nv_bfloat16* src =
                g_Ebf + (size_t)(nt * 128 + ldR) * D + c * 64 + ldKq;
            uint32_t dst = sB + (uint32_t)((s & (NSTAGE - 1)) * BSTG_HALVES) * 2
                              + (uint32_t)(ldR * B_STRIDE + ldKq) * 2;
            #pragma unroll
            for (int l = 0; l < 4; l++) {
                CP_ASYNC16(dst + (uint32_t)(32 * B_STRIDE * 2) * l,
                           src + (size_t)(32 * l) * D);
            }
        }
        CP_COMMIT();
    };

    // prologue: stages 0..NSTAGE-2 in flight
    issue(0); issue(1); issue(2);

    // load + convert A: X[rowBase..+128][0..512) -> bf16 smem (off critical path)
    #pragma unroll 4
    for (int i = 0; i < 64; i++) {
        int f = tid + i * 256;          // float4 id: 128 per row
        int r = f >> 7;
        int k = (f & 127) << 2;
        float4 v = *reinterpret_cast<const float4*>(&X[(size_t)(rowBase + r) * D + k]);
        __nv_bfloat162 p0 = __floats2bfloat162_rn(v.x, v.y);
        __nv_bfloat162 p1 = __floats2bfloat162_rn(v.z, v.w);
        *reinterpret_cast<__nv_bfloat162*>(&Asm[r * A_STRIDE + k])     = p0;
        *reinterpret_cast<__nv_bfloat162*>(&Asm[r * A_STRIDE + k + 2]) = p1;
    }
    for (int i = tid; i < KCODES; i += 256) esm[i] = g_eSq[i];
    __syncthreads();   // A + esm visible to all warps

    // per-lane ldmatrix address components
    const int aRowLane = ((lane >> 3) & 1) * 8 + (lane & 7);
    const int aKLane   = ((lane >> 4) & 1) * 8;
    const int bRowLane = lane & 7;
    const int bKLane   = ((lane >> 3) & 1) * 8;

    float acc[4][4][4];
    #pragma unroll
    for (int mi = 0; mi < 4; mi++)
        #pragma unroll
        for (int ni = 0; ni < 4; ni++)
            #pragma unroll
            for (int q = 0; q < 4; q++) acc[mi][ni][q] = 0.0f;

    for (int s = 0; s < 64; s++) {
        const int nt = s >> 3, c = s & 7;
        CP_WAIT(NSTAGE - 2);    // stage s complete (this thread's groups)
        __syncthreads();        // publish stage s; all warps done with stage s-1
        issue(s + NSTAGE - 1);  // overwrites buf (s-1)%4 -- safe post-sync

        const uint32_t bufB = sB + (uint32_t)((s & (NSTAGE - 1)) * BSTG_HALVES) * 2;
        #pragma unroll
        for (int ks = 0; ks < 4; ks++) {
            uint32_t afr[4][4];
            const int kk = c * 64 + ks * 16 + aKLane;
            #pragma unroll
            for (int mi = 0; mi < 4; mi++) {
                int r = wm * 64 + mi * 16 + aRowLane;
                ldmatrix_x4(afr[mi], sA + (uint32_t)(r * A_STRIDE + kk) * 2);
            }
            uint32_t bfr[4][2];
            const int kb = ks * 16 + bKLane;
            #pragma unroll
            for (int ni = 0; ni < 4; ni++) {
                int r = wn * 32 + ni * 8 + bRowLane;
                ldmatrix_x2(bfr[ni], bufB + (uint32_t)(r * B_STRIDE + kb) * 2);
            }
            #pragma unroll
            for (int mi = 0; mi < 4; mi++)
                #pragma unroll
                for (int ni = 0; ni < 4; ni++)
                    mma_bf16(acc[mi][ni], afr[mi], bfr[ni]);
        }

        if (c == 7) {
            // epilogue for tile nt: s = esq - 2*dot -> bf16 score matrix
            const int nbase = nt * 128;
            #pragma unroll
            for (int mi = 0; mi < 4; mi++) {
                int r0 = rowBase + wm * 64 + mi * 16 + (lane >> 2);
                #pragma unroll
                for (int ni = 0; ni < 4; ni++) {
                    int col = nbase + wn * 32 + ni * 8 + (lane & 3) * 2;
                    float es0 = esm[col], es1 = esm[col + 1];
                    __nv_bfloat162 lo = __floats2bfloat162_rn(
                        es0 - 2.0f * acc[mi][ni][0], es1 - 2.0f * acc[mi][ni][1]);
                    __nv_bfloat162 hi = __floats2bfloat162_rn(
                        es0 - 2.0f * acc[mi][ni][2], es1 - 2.0f * acc[mi][ni][3]);
                    *reinterpret_cast<__nv_bfloat162*>(
                        &g_scoresh[(size_t)r0 * KCODES + col]) = lo;
                    *reinterpret_cast<__nv_bfloat162*>(
                        &g_scoresh[(size_t)(r0 + 8) * KCODES + col]) = hi;
                    acc[mi][ni][0] = 0.0f; acc[mi][ni][1] = 0.0f;
                    acc[mi][ni][2] = 0.0f; acc[mi][ni][3] = 0.0f;
                }
            }
        }
    }
}

// ---------------------------------------------------------------------------
// Kernel 3: SELECT + EXACT + GATHER + LOSS.  One block (128 thr) per row.
//  - screened min over bf16 scores; candidates = { s < min + MARGIN }
//    (bf16 dot err <=~4e-4 + bf16 storage err <=1.2e-4  <<  MARGIN)
//  - exact fp32 dot for candidates; quantized score fl((xsq+esq)-fl(2*dot));
//    argmin with first-index tie-break == reference
//  - write quantized row (scalar stores: outQ only 4B-aligned), index, loss
// ---------------------------------------------------------------------------
#define MAXCAND 32
__global__ __launch_bounds__(128)
void select_kernel(const float* __restrict__ X, const float* __restrict__ E,
                   float* __restrict__ outQ, float* __restrict__ outIdx) {
    const int row  = blockIdx.x;
    const int t    = threadIdx.x;
    const int lane = t & 31;
    const int wid  = t >> 5;

    __shared__ float xrow[512];
    __shared__ float wred[4];
    __shared__ int   cand[MAXCAND];
    __shared__ float cval[MAXCAND];
    __shared__ int   ccnt;
    __shared__ int   bestIdx_s;
    __shared__ float fbV[128];
    __shared__ int   fbI[128];

    // load X row (float4 -> smem)
    float4 xv = reinterpret_cast<const float4*>(X + (size_t)row * D)[t];
    *reinterpret_cast<float4*>(&xrow[t * 4]) = xv;
    if (t == 0) ccnt = 0;

    // load 8 bf16 scores per thread, local min
    const __nv_bfloat16* srow = g_scoresh + (size_t)row * KCODES;
    uint4 raw = reinterpret_cast<const uint4*>(srow)[t];
    float sv[8];
    {
        __nv_bfloat162 h0 = *reinterpret_cast<__nv_bfloat162*>(&raw.x);
        __nv_bfloat162 h1 = *reinterpret_cast<__nv_bfloat162*>(&raw.y);
        __nv_bfloat162 h2 = *reinterpret_cast<__nv_bfloat162*>(&raw.z);
        __nv_bfloat162 h3 = *reinterpret_cast<__nv_bfloat162*>(&raw.w);
        sv[0] = __bfloat162float(h0.x); sv[1] = __bfloat162float(h0.y);
        sv[2] = __bfloat162float(h1.x); sv[3] = __bfloat162float(h1.y);
        sv[4] = __bfloat162float(h2.x); sv[5] = __bfloat162float(h2.y);
        sv[6] = __bfloat162float(h3.x); sv[7] = __bfloat162float(h3.y);
    }
    float m = sv[0];
    #pragma unroll
    for (int j = 1; j < 8; j++) m = fminf(m, sv[j]);
    #pragma unroll
    for (int off = 16; off > 0; off >>= 1)
        m = fminf(m, __shfl_xor_sync(0xFFFFFFFFu, m, off));
    if (lane == 0) wred[wid] = m;
    __syncthreads();
    m = fminf(fminf(wred[0], wred[1]), fminf(wred[2], wred[3]));
    const float thresh = m + MARGIN;

    // collect candidates (8 consecutive codes per thread)
    #pragma unroll
    for (int j = 0; j < 8; j++) {
        if (sv[j] < thresh) {
            int slot = atomicAdd(&ccnt, 1);
            if (slot < MAXCAND) cand[slot] = t * 8 + j;
        }
    }
    __syncthreads();
    int cnt = ccnt;
    const float xs = g_xSq[row];

    if (cnt <= MAXCAND) {
        // exact per candidate: warp w handles candidates w, w+4, ...
        for (int i = wid; i < cnt; i += 4) {
            int code = cand[i];
            const float* e = E + (size_t)code * D;
            float p = 0.0f;
            #pragma unroll 4
            for (int j = lane; j < D; j += 32) p = fmaf(xrow[j], e[j], p);
            #pragma unroll
            for (int off = 16; off > 0; off >>= 1)
                p += __shfl_xor_sync(0xFFFFFFFFu, p, off);
            if (lane == 0)
                cval[i] = __fsub_rn(__fadd_rn(xs, g_eSq[code]),
                                    __fmul_rn(2.0f, p));
        }
        __syncthreads();
        if (t == 0) {
            float bv = CUDART_INF_F; int bi = 0x7fffffff;
            for (int i = 0; i < cnt; i++) {
                float v = cval[i]; int ix = cand[i];
                if (v < bv || (v == bv && ix < bi)) { bv = v; bi = ix; }
            }
            bestIdx_s = bi;
        }
    } else {
        // overflow fallback (rare): full exact scan, 8 codes per thread
        float bv = CUDART_INF_F; int bi = 0x7fffffff;
        for (int j = 0; j < 8; j++) {
            int code = t * 8 + j;
            const float* e = E + (size_t)code * D;
            float p = 0.0f;
            for (int k = 0; k < D; k++) p = fmaf(xrow[k], e[k], p);
            float v = __fsub_rn(__fadd_rn(xs, g_eSq[code]), __fmul_rn(2.0f, p));
            if (v < bv || (v == bv && code < bi)) { bv = v; bi = code; }
        }
        fbV[t] = bv; fbI[t] = bi;
        __syncthreads();
        if (t == 0) {
            for (int i = 1; i < 128; i++) {
                if (fbV[i] < bv || (fbV[i] == bv && fbI[i] < bi)) {
                    bv = fbV[i]; bi = fbI[i];
                }
            }
            bestIdx_s = bi;
        }
    }
    __syncthreads();
    const int bi = bestIdx_s;

    // gather + loss
    float4 ev = reinterpret_cast<const float4*>(E + (size_t)bi * D)[t];
    float* q = outQ + (size_t)row * D;
    q[t * 4 + 0] = ev.x; q[t * 4 + 1] = ev.y;
    q[t * 4 + 2] = ev.z; q[t * 4 + 3] = ev.w;
    float dx = ev.x - xv.x, dy = ev.y - xv.y, dz = ev.z - xv.z, dw = ev.w - xv.w;
    float s = dx * dx + dy * dy + dz * dz + dw * dw;
    #pragma unroll
    for (int off = 16; off > 0; off >>= 1)
        s += __shfl_down_sync(0xFFFFFFFFu, s, off);
    if (lane == 0) wred[wid] = s;
    __syncthreads();
    if (t == 0) {
        atomicAdd(&g_acc, (double)(wred[0] + wred[1] + wred[2] + wred[3]));
        outIdx[row] = (float)bi;
    }
}

// ---------------------------------------------------------------------------
// Kernel 4: finalize loss = 1.25 * mean((q-x)^2)
// ---------------------------------------------------------------------------
__global__ void finalize_kernel(float* __restrict__ outLoss, int n) {
    outLoss[0] = (float)(1.25 * g_acc / ((double)n * (double)D));
}

// ---------------------------------------------------------------------------
extern "C" void kernel_launch(void* const* d_in, const int* in_sizes, int n_in,
                              void* d_out, int out_size) {
    const float* X = (const float*)d_in[0];   // [N, 512]
    const float* E = (const float*)d_in[1];   // [1024, 512]

    const int N = in_sizes[0] / D;            // 16384

    float* out      = (float*)d_out;
    float* outLoss  = out;
    float* outQ     = out + 1;
    float* outIdx   = out + 1 + (size_t)N * D;

    cudaFuncSetAttribute(screen_kernel,
                         cudaFuncAttributeMaxDynamicSharedMemorySize, SM_SCR_TOTAL);

    zero_kernel<<<1, 1>>>();
    esq_kernel<<<KCODES, 128>>>(E);
    xsq_kernel<<<N / 8, 256>>>(X);
    screen_kernel<<<N / 128, 256, SM_SCR_TOTAL>>>(X);
    select_kernel<<<N, 128>>>(X, E, outQ, outIdx);
    finalize_kernel<<<1, 1>>>(outLoss, N);
}